// round 3
// baseline (speedup 1.0000x reference)
#include <cuda_runtime.h>
#include <cstdint>

// Problem constants (fixed by the dataset)
#define E_   8
#define T_   8192
#define HD   1024
#define FH   4096
#define CAP  8192          // per-expert entry capacity (worst case: all tokens pick one expert)
#define HROWS 17408        // 16384 entries + up to 8*128 padding rows

// ---------------- device scratch (allocation-free contract) ----------------
__device__ int   g_count[E_];
__device__ int   g_off[E_];
__device__ int   g_idx[E_ * CAP];
__device__ float g_wgt[E_ * CAP];
__device__ float g_hid[(size_t)HROWS * FH];   // ~285 MB hidden scratch (tf32-rounded, gate-weighted)

// ---------------- helpers ----------------
__device__ __forceinline__ uint32_t f2tf(float x) {
    uint32_t r;
    asm("cvt.rna.tf32.f32 %0, %1;" : "=r"(r) : "f"(x));
    return r;
}

__device__ __forceinline__ void mma8(float* c, const uint32_t* a, const uint32_t* b) {
    asm volatile(
        "mma.sync.aligned.m16n8k8.row.col.f32.tf32.tf32.f32 "
        "{%0,%1,%2,%3},{%4,%5,%6,%7},{%8,%9},{%0,%1,%2,%3};"
        : "+f"(c[0]), "+f"(c[1]), "+f"(c[2]), "+f"(c[3])
        : "r"(a[0]), "r"(a[1]), "r"(a[2]), "r"(a[3]),
          "r"(b[0]), "r"(b[1]));
}

// ---------------- kernels ----------------
__global__ void init_counts_kernel() {
    if ((int)threadIdx.x < E_) g_count[threadIdx.x] = 0;
}

// One warp per token: 8 logits, top-2, pair-renormalized softmax weights.
__global__ void router_kernel(const float* __restrict__ x, const float* __restrict__ gw) {
    int warp = (blockIdx.x * blockDim.x + threadIdx.x) >> 5;
    int lane = threadIdx.x & 31;
    if (warp >= T_) return;
    const float* xr = x + (size_t)warp * HD;

    float acc[E_];
#pragma unroll
    for (int e = 0; e < E_; e++) acc[e] = 0.f;

    for (int k = lane; k < HD; k += 32) {
        float xv = xr[k];
        const float4* g = (const float4*)(gw + (size_t)k * E_);
        float4 g0 = g[0], g1 = g[1];
        acc[0] += xv * g0.x; acc[1] += xv * g0.y; acc[2] += xv * g0.z; acc[3] += xv * g0.w;
        acc[4] += xv * g1.x; acc[5] += xv * g1.y; acc[6] += xv * g1.z; acc[7] += xv * g1.w;
    }
#pragma unroll
    for (int off = 16; off; off >>= 1) {
#pragma unroll
        for (int e = 0; e < E_; e++) acc[e] += __shfl_xor_sync(0xffffffffu, acc[e], off);
    }

    if (lane == 0) {
        int e0 = 0; float l0 = acc[0];
#pragma unroll
        for (int e = 1; e < E_; e++) if (acc[e] > l0) { l0 = acc[e]; e0 = e; }
        int e1 = -1; float l1 = -3.4e38f;
#pragma unroll
        for (int e = 0; e < E_; e++) if (e != e0 && acc[e] > l1) { l1 = acc[e]; e1 = e; }
        // top-2 of softmax renormalized == pair softmax of logits
        float w0 = 1.0f / (1.0f + expf(l1 - l0));
        float w1 = 1.0f - w0;
        int p0 = atomicAdd(&g_count[e0], 1);
        g_idx[e0 * CAP + p0] = warp; g_wgt[e0 * CAP + p0] = w0;
        int p1 = atomicAdd(&g_count[e1], 1);
        g_idx[e1 * CAP + p1] = warp; g_wgt[e1 * CAP + p1] = w1;
    }
}

__global__ void calc_offsets_kernel() {
    if (threadIdx.x == 0) {
        int o = 0;
        for (int e = 0; e < E_; e++) {
            g_off[e] = o;
            o += (g_count[e] + 127) & ~127;
        }
    }
}

// Grouped GEMM, 128x128x16 tiles, tf32 mma.sync, 2-stage cp.async pipeline.
// MODE==1: H = relu(X_gather @ W1[e])^2 * gate_w  -> g_hid (tf32-rounded)
// MODE==2: OUT += H @ W2[e], scatter via atomicAdd
template <int MODE>
__global__ __launch_bounds__(256, 2)
void moe_gemm_kernel(const float* __restrict__ Asrc,
                     const float* __restrict__ Wsrc,
                     float* __restrict__ out) {
    constexpr int KTOT = (MODE == 1) ? HD : FH;
    constexpr int LDB  = (MODE == 1) ? FH : HD;
    constexpr int KT   = KTOT / 16;

    const int e   = blockIdx.z;
    const int cnt = g_count[e];
    const int m0  = blockIdx.y * 128;
    if (m0 >= cnt) return;
    const int n0  = blockIdx.x * 128;

    __shared__ __align__(16) float As[2][128][20];   // pad 20 -> conflict-free A frags
    __shared__ __align__(16) float Bs[2][16][136];   // pad 136 -> conflict-free B frags
    __shared__ int   srow[128];
    __shared__ float swt[128];

    const int tid  = threadIdx.x;
    const int lane = tid & 31;
    const int wid  = tid >> 5;

    if (tid < 128) {
        int j = m0 + tid;
        if constexpr (MODE == 1) {
            int jj = (j < cnt) ? j : (cnt - 1);     // clamp padded rows (finite garbage, never used)
            srow[tid] = g_idx[e * CAP + jj];
            swt[tid]  = g_wgt[e * CAP + jj];
        } else {
            srow[tid] = (j < cnt) ? g_idx[e * CAP + j] : -1;
        }
    }
    __syncthreads();

    // load assignments: each thread owns 2 A rows (16B each) + 2 B rows (16B each) per k-tile
    const int arow0 = tid >> 2, arow1 = arow0 + 64, apart = tid & 3;
    const float* gA0;
    const float* gA1;
    if constexpr (MODE == 1) {
        gA0 = Asrc + (size_t)srow[arow0] * HD + apart * 4;
        gA1 = Asrc + (size_t)srow[arow1] * HD + apart * 4;
    } else {
        (void)Asrc;
        const int base = g_off[e] + m0;
        gA0 = g_hid + (size_t)(base + arow0) * FH + apart * 4;
        gA1 = g_hid + (size_t)(base + arow1) * FH + apart * 4;
    }
    const int bkr = tid >> 5, bcc = tid & 31;
    const float* gB0 = Wsrc + (size_t)e * KTOT * LDB + (size_t)bkr * LDB + n0 + bcc * 4;
    const float* gB1 = gB0 + (size_t)8 * LDB;

    uint32_t sa0[2], sa1[2], sb0[2], sb1[2];
#pragma unroll
    for (int b = 0; b < 2; b++) {
        sa0[b] = (uint32_t)__cvta_generic_to_shared(&As[b][arow0][apart * 4]);
        sa1[b] = (uint32_t)__cvta_generic_to_shared(&As[b][arow1][apart * 4]);
        sb0[b] = (uint32_t)__cvta_generic_to_shared(&Bs[b][bkr][bcc * 4]);
        sb1[b] = (uint32_t)__cvta_generic_to_shared(&Bs[b][bkr + 8][bcc * 4]);
    }

    auto issue = [&](int kt, int b) {
        const float* pa0 = gA0 + kt * 16;
        const float* pa1 = gA1 + kt * 16;
        const float* pb0 = gB0 + (size_t)kt * 16 * LDB;
        const float* pb1 = gB1 + (size_t)kt * 16 * LDB;
        asm volatile("cp.async.cg.shared.global [%0],[%1],16;" :: "r"(sa0[b]), "l"(pa0));
        asm volatile("cp.async.cg.shared.global [%0],[%1],16;" :: "r"(sa1[b]), "l"(pa1));
        asm volatile("cp.async.cg.shared.global [%0],[%1],16;" :: "r"(sb0[b]), "l"(pb0));
        asm volatile("cp.async.cg.shared.global [%0],[%1],16;" :: "r"(sb1[b]), "l"(pb1));
        asm volatile("cp.async.commit_group;");
    };

    issue(0, 0);

    const int warp_m = wid & 1, warp_n = wid >> 1;
    const int gid = lane >> 2, tig = lane & 3;
    const int rbase = warp_m * 64;
    const int cbase = warp_n * 32;

    float acc[4][4][4];
#pragma unroll
    for (int i = 0; i < 4; i++)
#pragma unroll
        for (int j = 0; j < 4; j++)
#pragma unroll
            for (int q = 0; q < 4; q++) acc[i][j][q] = 0.f;

    for (int kt = 0; kt < KT; ++kt) {
        const int buf = kt & 1;
        if (kt + 1 < KT) {
            issue(kt + 1, buf ^ 1);
            asm volatile("cp.async.wait_group 1;" ::: "memory");
        } else {
            asm volatile("cp.async.wait_group 0;" ::: "memory");
        }
        __syncthreads();

#pragma unroll
        for (int ks = 0; ks < 2; ++ks) {
            uint32_t af[4][4];
#pragma unroll
            for (int ms = 0; ms < 4; ++ms) {
                const int r = rbase + ms * 16 + gid;
                const int c = ks * 8 + tig;
                float a0 = As[buf][r][c],     a1 = As[buf][r + 8][c];
                float a2 = As[buf][r][c + 4], a3 = As[buf][r + 8][c + 4];
                if constexpr (MODE == 1) {
                    af[ms][0] = f2tf(a0); af[ms][1] = f2tf(a1);
                    af[ms][2] = f2tf(a2); af[ms][3] = f2tf(a3);
                } else {  // hidden already tf32-rounded
                    af[ms][0] = __float_as_uint(a0); af[ms][1] = __float_as_uint(a1);
                    af[ms][2] = __float_as_uint(a2); af[ms][3] = __float_as_uint(a3);
                }
            }
            uint32_t bf[4][2];
#pragma unroll
            for (int ns = 0; ns < 4; ++ns) {
                const int cc = cbase + ns * 8 + gid;
                const int rr = ks * 8 + tig;
                bf[ns][0] = f2tf(Bs[buf][rr][cc]);
                bf[ns][1] = f2tf(Bs[buf][rr + 4][cc]);
            }
#pragma unroll
            for (int ms = 0; ms < 4; ++ms)
#pragma unroll
                for (int ns = 0; ns < 4; ++ns)
                    mma8(acc[ms][ns], af[ms], bf[ns]);
        }
        __syncthreads();
    }

    // ---------------- epilogue ----------------
    if constexpr (MODE == 1) {
        const int hb = g_off[e] + m0;
#pragma unroll
        for (int ms = 0; ms < 4; ++ms) {
            const int lr = rbase + ms * 16 + gid;
            const float wA = swt[lr], wB = swt[lr + 8];
#pragma unroll
            for (int ns = 0; ns < 4; ++ns) {
                const int c = n0 + cbase + ns * 8 + tig * 2;
                float v0 = fmaxf(acc[ms][ns][0], 0.f); v0 = v0 * v0 * wA;
                float v1 = fmaxf(acc[ms][ns][1], 0.f); v1 = v1 * v1 * wA;
                float v2 = fmaxf(acc[ms][ns][2], 0.f); v2 = v2 * v2 * wB;
                float v3 = fmaxf(acc[ms][ns][3], 0.f); v3 = v3 * v3 * wB;
                float2 p0 = make_float2(__uint_as_float(f2tf(v0)), __uint_as_float(f2tf(v1)));
                float2 p1 = make_float2(__uint_as_float(f2tf(v2)), __uint_as_float(f2tf(v3)));
                *(float2*)&g_hid[(size_t)(hb + lr) * FH + c]     = p0;
                *(float2*)&g_hid[(size_t)(hb + lr + 8) * FH + c] = p1;
            }
        }
    } else {
#pragma unroll
        for (int ms = 0; ms < 4; ++ms) {
            const int lr = rbase + ms * 16 + gid;
            const int t0 = srow[lr], t1 = srow[lr + 8];
#pragma unroll
            for (int ns = 0; ns < 4; ++ns) {
                const int c = n0 + cbase + ns * 8 + tig * 2;
                if (t0 >= 0) {
                    atomicAdd(&out[(size_t)t0 * HD + c],     acc[ms][ns][0]);
                    atomicAdd(&out[(size_t)t0 * HD + c + 1], acc[ms][ns][1]);
                }
                if (t1 >= 0) {
                    atomicAdd(&out[(size_t)t1 * HD + c],     acc[ms][ns][2]);
                    atomicAdd(&out[(size_t)t1 * HD + c + 1], acc[ms][ns][3]);
                }
            }
        }
    }
}

// ---------------- launch ----------------
extern "C" void kernel_launch(void* const* d_in, const int* in_sizes, int n_in,
                              void* d_out, int out_size) {
    const float* x  = (const float*)d_in[0];   // [4,2048,1024]
    const float* gw = (const float*)d_in[1];   // [1024,8]
    const float* w1 = (const float*)d_in[2];   // [8,1024,4096]
    const float* w2 = (const float*)d_in[3];   // [8,4096,1024]
    float* out = (float*)d_out;                // [4,2048,1024] f32
    (void)in_sizes; (void)n_in;

    cudaMemsetAsync(d_out, 0, (size_t)out_size * sizeof(float), 0);
    init_counts_kernel<<<1, 32>>>();
    router_kernel<<<T_ / 8, 256>>>(x, gw);
    calc_offsets_kernel<<<1, 1>>>();
    // GEMM1: [cnt,1024] x [1024,4096] per expert -> hidden scratch
    moe_gemm_kernel<1><<<dim3(FH / 128, T_ / 128, E_), 256>>>(x, w1, out);
    // GEMM2: [cnt,4096] x [4096,1024] per expert -> scatter-add into out
    moe_gemm_kernel<2><<<dim3(HD / 128, T_ / 128, E_), 256>>>(nullptr, w2, out);
}

// round 4
// speedup vs baseline: 1.0059x; 1.0059x over previous
#include <cuda_runtime.h>
#include <cstdint>

// Problem constants (fixed by the dataset)
#define E_   8
#define T_   8192
#define HD   1024
#define FH   4096
#define CAP  8192          // per-expert entry capacity (worst case: all tokens pick one expert)
#define HROWS 17408        // 16384 entries + up to 8*128 padding rows

// ---------------- device scratch (allocation-free contract) ----------------
__device__ int   g_count[E_];
__device__ int   g_off[E_];
__device__ int   g_idx[E_ * CAP];
__device__ float g_wgt[E_ * CAP];
__device__ float g_hid[(size_t)HROWS * FH];   // ~285 MB hidden scratch (tf32-rounded, gate-weighted)

// ---------------- helpers ----------------
__device__ __forceinline__ uint32_t f2tf(float x) {
    uint32_t r;
    asm("cvt.rna.tf32.f32 %0, %1;" : "=r"(r) : "f"(x));
    return r;
}

__device__ __forceinline__ void mma8(float* c, const uint32_t* a, const uint32_t* b) {
    asm volatile(
        "mma.sync.aligned.m16n8k8.row.col.f32.tf32.tf32.f32 "
        "{%0,%1,%2,%3},{%4,%5,%6,%7},{%8,%9},{%0,%1,%2,%3};"
        : "+f"(c[0]), "+f"(c[1]), "+f"(c[2]), "+f"(c[3])
        : "r"(a[0]), "r"(a[1]), "r"(a[2]), "r"(a[3]),
          "r"(b[0]), "r"(b[1]));
}

// ---------------- kernels ----------------
__global__ void init_counts_kernel() {
    if ((int)threadIdx.x < E_) g_count[threadIdx.x] = 0;
}

// One warp per token: 8 logits, top-2, pair-renormalized softmax weights.
__global__ void router_kernel(const float* __restrict__ x, const float* __restrict__ gw) {
    int warp = (blockIdx.x * blockDim.x + threadIdx.x) >> 5;
    int lane = threadIdx.x & 31;
    if (warp >= T_) return;
    const float* xr = x + (size_t)warp * HD;

    float acc[E_];
#pragma unroll
    for (int e = 0; e < E_; e++) acc[e] = 0.f;

    for (int k = lane; k < HD; k += 32) {
        float xv = xr[k];
        const float4* g = (const float4*)(gw + (size_t)k * E_);
        float4 g0 = g[0], g1 = g[1];
        acc[0] += xv * g0.x; acc[1] += xv * g0.y; acc[2] += xv * g0.z; acc[3] += xv * g0.w;
        acc[4] += xv * g1.x; acc[5] += xv * g1.y; acc[6] += xv * g1.z; acc[7] += xv * g1.w;
    }
#pragma unroll
    for (int off = 16; off; off >>= 1) {
#pragma unroll
        for (int e = 0; e < E_; e++) acc[e] += __shfl_xor_sync(0xffffffffu, acc[e], off);
    }

    if (lane == 0) {
        int e0 = 0; float l0 = acc[0];
#pragma unroll
        for (int e = 1; e < E_; e++) if (acc[e] > l0) { l0 = acc[e]; e0 = e; }
        int e1 = -1; float l1 = -3.4e38f;
#pragma unroll
        for (int e = 0; e < E_; e++) if (e != e0 && acc[e] > l1) { l1 = acc[e]; e1 = e; }
        // top-2 of softmax renormalized == pair softmax of logits
        float w0 = 1.0f / (1.0f + expf(l1 - l0));
        float w1 = 1.0f - w0;
        int p0 = atomicAdd(&g_count[e0], 1);
        g_idx[e0 * CAP + p0] = warp; g_wgt[e0 * CAP + p0] = w0;
        int p1 = atomicAdd(&g_count[e1], 1);
        g_idx[e1 * CAP + p1] = warp; g_wgt[e1 * CAP + p1] = w1;
    }
}

__global__ void calc_offsets_kernel() {
    if (threadIdx.x == 0) {
        int o = 0;
        for (int e = 0; e < E_; e++) {
            g_off[e] = o;
            o += (g_count[e] + 127) & ~127;
        }
    }
}

// Grouped GEMM, 128x128x16 tiles, tf32 mma.sync, 2-stage cp.async pipeline.
// MODE==1: H = relu(X_gather @ W1[e])^2 * gate_w  -> g_hid (tf32-rounded)
// MODE==2: OUT += H @ W2[e], scatter via atomicAdd
template <int MODE>
__global__ __launch_bounds__(256, 2)
void moe_gemm_kernel(const float* __restrict__ Asrc,
                     const float* __restrict__ Wsrc,
                     float* __restrict__ out) {
    constexpr int KTOT = (MODE == 1) ? HD : FH;
    constexpr int LDB  = (MODE == 1) ? FH : HD;
    constexpr int KT   = KTOT / 16;

    const int e   = blockIdx.z;
    const int cnt = g_count[e];
    const int m0  = blockIdx.y * 128;
    if (m0 >= cnt) return;
    const int n0  = blockIdx.x * 128;

    __shared__ __align__(16) float As[2][128][20];   // pad 20 -> conflict-free A frags
    __shared__ __align__(16) float Bs[2][16][136];   // pad 136 -> conflict-free B frags
    __shared__ int   srow[128];
    __shared__ float swt[128];

    const int tid  = threadIdx.x;
    const int lane = tid & 31;
    const int wid  = tid >> 5;

    if (tid < 128) {
        int j = m0 + tid;
        if constexpr (MODE == 1) {
            int jj = (j < cnt) ? j : (cnt - 1);     // clamp padded rows (finite garbage, never used)
            srow[tid] = g_idx[e * CAP + jj];
            swt[tid]  = g_wgt[e * CAP + jj];
        } else {
            srow[tid] = (j < cnt) ? g_idx[e * CAP + j] : -1;
        }
    }
    __syncthreads();

    // load assignments: each thread owns 2 A rows (16B each) + 2 B rows (16B each) per k-tile
    const int arow0 = tid >> 2, arow1 = arow0 + 64, apart = tid & 3;
    const float* gA0;
    const float* gA1;
    if constexpr (MODE == 1) {
        gA0 = Asrc + (size_t)srow[arow0] * HD + apart * 4;
        gA1 = Asrc + (size_t)srow[arow1] * HD + apart * 4;
    } else {
        (void)Asrc;
        const int base = g_off[e] + m0;
        gA0 = g_hid + (size_t)(base + arow0) * FH + apart * 4;
        gA1 = g_hid + (size_t)(base + arow1) * FH + apart * 4;
    }
    const int bkr = tid >> 5, bcc = tid & 31;
    const float* gB0 = Wsrc + (size_t)e * KTOT * LDB + (size_t)bkr * LDB + n0 + bcc * 4;
    const float* gB1 = gB0 + (size_t)8 * LDB;

    uint32_t sa0[2], sa1[2], sb0[2], sb1[2];
#pragma unroll
    for (int b = 0; b < 2; b++) {
        sa0[b] = (uint32_t)__cvta_generic_to_shared(&As[b][arow0][apart * 4]);
        sa1[b] = (uint32_t)__cvta_generic_to_shared(&As[b][arow1][apart * 4]);
        sb0[b] = (uint32_t)__cvta_generic_to_shared(&Bs[b][bkr][bcc * 4]);
        sb1[b] = (uint32_t)__cvta_generic_to_shared(&Bs[b][bkr + 8][bcc * 4]);
    }

    auto issue = [&](int kt, int b) {
        const float* pa0 = gA0 + kt * 16;
        const float* pa1 = gA1 + kt * 16;
        const float* pb0 = gB0 + (size_t)kt * 16 * LDB;
        const float* pb1 = gB1 + (size_t)kt * 16 * LDB;
        asm volatile("cp.async.cg.shared.global [%0],[%1],16;" :: "r"(sa0[b]), "l"(pa0));
        asm volatile("cp.async.cg.shared.global [%0],[%1],16;" :: "r"(sa1[b]), "l"(pa1));
        asm volatile("cp.async.cg.shared.global [%0],[%1],16;" :: "r"(sb0[b]), "l"(pb0));
        asm volatile("cp.async.cg.shared.global [%0],[%1],16;" :: "r"(sb1[b]), "l"(pb1));
        asm volatile("cp.async.commit_group;");
    };

    issue(0, 0);

    const int warp_m = wid & 1, warp_n = wid >> 1;
    const int gid = lane >> 2, tig = lane & 3;
    const int rbase = warp_m * 64;
    const int cbase = warp_n * 32;

    float acc[4][4][4];
#pragma unroll
    for (int i = 0; i < 4; i++)
#pragma unroll
        for (int j = 0; j < 4; j++)
#pragma unroll
            for (int q = 0; q < 4; q++) acc[i][j][q] = 0.f;

    for (int kt = 0; kt < KT; ++kt) {
        const int buf = kt & 1;
        if (kt + 1 < KT) {
            issue(kt + 1, buf ^ 1);
            asm volatile("cp.async.wait_group 1;" ::: "memory");
        } else {
            asm volatile("cp.async.wait_group 0;" ::: "memory");
        }
        __syncthreads();

#pragma unroll
        for (int ks = 0; ks < 2; ++ks) {
            uint32_t af[4][4];
#pragma unroll
            for (int ms = 0; ms < 4; ++ms) {
                const int r = rbase + ms * 16 + gid;
                const int c = ks * 8 + tig;
                float a0 = As[buf][r][c],     a1 = As[buf][r + 8][c];
                float a2 = As[buf][r][c + 4], a3 = As[buf][r + 8][c + 4];
                if constexpr (MODE == 1) {
                    af[ms][0] = f2tf(a0); af[ms][1] = f2tf(a1);
                    af[ms][2] = f2tf(a2); af[ms][3] = f2tf(a3);
                } else {  // hidden already tf32-rounded
                    af[ms][0] = __float_as_uint(a0); af[ms][1] = __float_as_uint(a1);
                    af[ms][2] = __float_as_uint(a2); af[ms][3] = __float_as_uint(a3);
                }
            }
            uint32_t bf[4][2];
#pragma unroll
            for (int ns = 0; ns < 4; ++ns) {
                const int cc = cbase + ns * 8 + gid;
                const int rr = ks * 8 + tig;
                bf[ns][0] = f2tf(Bs[buf][rr][cc]);
                bf[ns][1] = f2tf(Bs[buf][rr + 4][cc]);
            }
#pragma unroll
            for (int ms = 0; ms < 4; ++ms)
#pragma unroll
                for (int ns = 0; ns < 4; ++ns)
                    mma8(acc[ms][ns], af[ms], bf[ns]);
        }
        __syncthreads();
    }

    // ---------------- epilogue ----------------
    if constexpr (MODE == 1) {
        const int hb = g_off[e] + m0;
#pragma unroll
        for (int ms = 0; ms < 4; ++ms) {
            const int lr = rbase + ms * 16 + gid;
            const float wA = swt[lr], wB = swt[lr + 8];
#pragma unroll
            for (int ns = 0; ns < 4; ++ns) {
                const int c = n0 + cbase + ns * 8 + tig * 2;
                float v0 = fmaxf(acc[ms][ns][0], 0.f); v0 = v0 * v0 * wA;
                float v1 = fmaxf(acc[ms][ns][1], 0.f); v1 = v1 * v1 * wA;
                float v2 = fmaxf(acc[ms][ns][2], 0.f); v2 = v2 * v2 * wB;
                float v3 = fmaxf(acc[ms][ns][3], 0.f); v3 = v3 * v3 * wB;
                float2 p0 = make_float2(__uint_as_float(f2tf(v0)), __uint_as_float(f2tf(v1)));
                float2 p1 = make_float2(__uint_as_float(f2tf(v2)), __uint_as_float(f2tf(v3)));
                *(float2*)&g_hid[(size_t)(hb + lr) * FH + c]     = p0;
                *(float2*)&g_hid[(size_t)(hb + lr + 8) * FH + c] = p1;
            }
        }
    } else {
#pragma unroll
        for (int ms = 0; ms < 4; ++ms) {
            const int lr = rbase + ms * 16 + gid;
            const int t0 = srow[lr], t1 = srow[lr + 8];
#pragma unroll
            for (int ns = 0; ns < 4; ++ns) {
                const int c = n0 + cbase + ns * 8 + tig * 2;
                if (t0 >= 0) {
                    atomicAdd(&out[(size_t)t0 * HD + c],     acc[ms][ns][0]);
                    atomicAdd(&out[(size_t)t0 * HD + c + 1], acc[ms][ns][1]);
                }
                if (t1 >= 0) {
                    atomicAdd(&out[(size_t)t1 * HD + c],     acc[ms][ns][2]);
                    atomicAdd(&out[(size_t)t1 * HD + c + 1], acc[ms][ns][3]);
                }
            }
        }
    }
}

// ---------------- launch ----------------
extern "C" void kernel_launch(void* const* d_in, const int* in_sizes, int n_in,
                              void* d_out, int out_size) {
    const float* x  = (const float*)d_in[0];   // [4,2048,1024]
    const float* gw = (const float*)d_in[1];   // [1024,8]
    const float* w1 = (const float*)d_in[2];   // [8,1024,4096]
    const float* w2 = (const float*)d_in[3];   // [8,4096,1024]
    float* out = (float*)d_out;                // [4,2048,1024] f32
    (void)in_sizes; (void)n_in;

    cudaMemsetAsync(d_out, 0, (size_t)out_size * sizeof(float), 0);
    init_counts_kernel<<<1, 32>>>();
    router_kernel<<<T_ / 8, 256>>>(x, gw);
    calc_offsets_kernel<<<1, 1>>>();
    // GEMM1: [cnt,1024] x [1024,4096] per expert -> hidden scratch
    moe_gemm_kernel<1><<<dim3(FH / 128, T_ / 128, E_), 256>>>(x, w1, out);
    // GEMM2: [cnt,4096] x [4096,1024] per expert -> scatter-add into out
    moe_gemm_kernel<2><<<dim3(HD / 128, T_ / 128, E_), 256>>>(nullptr, w2, out);
}

// round 7
// speedup vs baseline: 1.7435x; 1.7333x over previous
#include <cuda_runtime.h>
#include <cuda_fp16.h>
#include <cstdint>

#define E_   8
#define T_   8192
#define HD   1024
#define FH   4096
#define CAP  8192
#define PADROWS 17408   // 16384 entries + up to 8*127 padding (128-aligned offsets)

// ---------------- device scratch ----------------
__device__ int    g_count[E_];
__device__ int    g_off[E_];
__device__ int    g_idx[E_ * CAP];
__device__ float  g_wgt[E_ * CAP];
__device__ int    g_tok_ent[T_ * 2];                  // (e<<16)|slot per token
__device__ __half g_xh [(size_t)T_ * HD];             // fp16 x
__device__ __half g_w1h[(size_t)E_ * FH * HD];        // w1 -> [e][n][k] fp16
__device__ __half g_w2h[(size_t)E_ * HD * FH];        // w2 -> [e][n][k] fp16
__device__ __half g_hid[(size_t)PADROWS * FH];        // hidden fp16 (gate-weighted)
__device__ float  g_o2 [(size_t)PADROWS * HD];        // per-entry GEMM2 output

// ---------------- helpers ----------------
__device__ __forceinline__ uint32_t smem_u32(const void* p) {
    uint32_t a;
    asm("{ .reg .u64 t; cvta.to.shared.u64 t, %1; cvt.u32.u64 %0, t; }" : "=r"(a) : "l"(p));
    return a;
}

#define CP_ASYNC16(dst, src) \
    asm volatile("cp.async.cg.shared.global [%0],[%1],16;" :: "r"(dst), "l"(src))
#define CP_COMMIT() asm volatile("cp.async.commit_group;" ::: "memory")

#define LDSM4(R0, R1, R2, R3, ADDR)                                            \
    asm volatile("ldmatrix.sync.aligned.m8n8.x4.shared.b16 {%0,%1,%2,%3},[%4];" \
        : "=r"(R0), "=r"(R1), "=r"(R2), "=r"(R3) : "r"(ADDR))

__device__ __forceinline__ void mma16816(float* c, const uint32_t* a, const uint32_t* b) {
    asm volatile(
        "mma.sync.aligned.m16n8k16.row.col.f32.f16.f16.f32 "
        "{%0,%1,%2,%3},{%4,%5,%6,%7},{%8,%9},{%0,%1,%2,%3};"
        : "+f"(c[0]), "+f"(c[1]), "+f"(c[2]), "+f"(c[3])
        : "r"(a[0]), "r"(a[1]), "r"(a[2]), "r"(a[3]), "r"(b[0]), "r"(b[1]));
}

// ---------------- small kernels ----------------
__global__ void init_counts_kernel() {
    if ((int)threadIdx.x < E_) g_count[threadIdx.x] = 0;
}

__global__ void router_kernel(const float* __restrict__ x, const float* __restrict__ gw) {
    int warp = (blockIdx.x * blockDim.x + threadIdx.x) >> 5;
    int lane = threadIdx.x & 31;
    if (warp >= T_) return;
    const float* xr = x + (size_t)warp * HD;
    float acc[E_];
#pragma unroll
    for (int e = 0; e < E_; e++) acc[e] = 0.f;
    for (int k = lane; k < HD; k += 32) {
        float xv = xr[k];
        const float4* g = (const float4*)(gw + (size_t)k * E_);
        float4 g0 = g[0], g1 = g[1];
        acc[0] += xv * g0.x; acc[1] += xv * g0.y; acc[2] += xv * g0.z; acc[3] += xv * g0.w;
        acc[4] += xv * g1.x; acc[5] += xv * g1.y; acc[6] += xv * g1.z; acc[7] += xv * g1.w;
    }
#pragma unroll
    for (int off = 16; off; off >>= 1)
#pragma unroll
        for (int e = 0; e < E_; e++) acc[e] += __shfl_xor_sync(0xffffffffu, acc[e], off);
    if (lane == 0) {
        int e0 = 0; float l0 = acc[0];
#pragma unroll
        for (int e = 1; e < E_; e++) if (acc[e] > l0) { l0 = acc[e]; e0 = e; }
        int e1 = -1; float l1 = -3.4e38f;
#pragma unroll
        for (int e = 0; e < E_; e++) if (e != e0 && acc[e] > l1) { l1 = acc[e]; e1 = e; }
        float w0 = 1.0f / (1.0f + expf(l1 - l0));
        float w1 = 1.0f - w0;
        int p0 = atomicAdd(&g_count[e0], 1);
        g_idx[e0 * CAP + p0] = warp; g_wgt[e0 * CAP + p0] = w0;
        int p1 = atomicAdd(&g_count[e1], 1);
        g_idx[e1 * CAP + p1] = warp; g_wgt[e1 * CAP + p1] = w1;
        g_tok_ent[warp * 2 + 0] = (e0 << 16) | p0;
        g_tok_ent[warp * 2 + 1] = (e1 << 16) | p1;
    }
}

__global__ void calc_offsets_kernel() {
    if (threadIdx.x == 0) {
        int o = 0;
        for (int e = 0; e < E_; e++) { g_off[e] = o; o += (g_count[e] + 127) & ~127; }
    }
}

__global__ void convert_x_kernel(const float4* __restrict__ x) {
    size_t i = (size_t)blockIdx.x * blockDim.x + threadIdx.x;
    float4 v = x[i];
    __half2* dst = (__half2*)g_xh;
    dst[i * 2 + 0] = __floats2half2_rn(v.x, v.y);
    dst[i * 2 + 1] = __floats2half2_rn(v.z, v.w);
}

// [e][K][N] fp32 -> [e][N][K] fp16. W=1: w1 (K=HD,N=FH). W=2: w2 (K=FH,N=HD).
template <int W>
__global__ void transpose_half_kernel(const float* __restrict__ in) {
    constexpr int K = (W == 1) ? HD : FH;
    constexpr int N = (W == 1) ? FH : HD;
    __half* out = (W == 1) ? g_w1h : g_w2h;
    __shared__ float tile[32][33];
    const int e = blockIdx.z;
    const float* inp = in + (size_t)e * K * N;
    __half* outp = out + (size_t)e * K * N;
    const int n0 = blockIdx.x * 32, k0 = blockIdx.y * 32;
    const int tx = threadIdx.x, ty = threadIdx.y;
#pragma unroll
    for (int i = 0; i < 32; i += 8)
        tile[ty + i][tx] = inp[(size_t)(k0 + ty + i) * N + n0 + tx];
    __syncthreads();
#pragma unroll
    for (int i = 0; i < 32; i += 8)
        outp[(size_t)(n0 + ty + i) * K + k0 + tx] = __float2half_rn(tile[tx][ty + i]);
}

__global__ void combine_kernel(float* __restrict__ out) {
    const int t = blockIdx.x;
    const int c = threadIdx.x * 4;
    int a = g_tok_ent[t * 2], b = g_tok_ent[t * 2 + 1];
    size_t r0 = (size_t)(g_off[a >> 16] + (a & 0xffff)) * HD;
    size_t r1 = (size_t)(g_off[b >> 16] + (b & 0xffff)) * HD;
    float4 u = *(const float4*)&g_o2[r0 + c];
    float4 v = *(const float4*)&g_o2[r1 + c];
    *(float4*)&out[(size_t)t * HD + c] =
        make_float4(u.x + v.x, u.y + v.y, u.z + v.z, u.w + v.w);
}

// ---------------- fp16 grouped GEMM: 128x128x32 tiles, 4-stage cp.async ------
// SMEM: A stages [4][128 rows][64B], B stages [4][128 rows][64B], swizzled.
// swizzle: element (r, k) chunk c = k>>3 stored at (c ^ ((r>>1)&3)) * 16B.
#define NSTG 4
#define STG_BYTES 8192
#define SMEM_A_OFF 0
#define SMEM_B_OFF (NSTG * STG_BYTES)
#define SMEM_SROW  (2 * NSTG * STG_BYTES)
#define SMEM_SWT   (SMEM_SROW + 512)
#define SMEM_TOTAL (SMEM_SWT + 512)

// MODE 1: g_hid = fp16(relu(x_gather @ w1h^T)^2 * gate)   [KTOT=1024, NB=4096]
// MODE 2: g_o2  = g_hid @ w2h^T                           [KTOT=4096, NB=1024]
template <int MODE>
__global__ __launch_bounds__(256, 2)
void moe_hgemm_kernel() {
    constexpr int KTOT = (MODE == 1) ? HD : FH;
    constexpr int NB   = (MODE == 1) ? FH : HD;
    constexpr int KT   = KTOT / 32;

    extern __shared__ char smem[];
    const int e   = blockIdx.z;
    const int cnt = g_count[e];
    const int m0  = blockIdx.y * 128;
    if (m0 >= cnt) return;
    const int n0  = blockIdx.x * 128;
    const int hb  = g_off[e] + m0;

    const int tid = threadIdx.x, lane = tid & 31, wid = tid >> 5;
    int*   srow = (int*)(smem + SMEM_SROW);
    float* swt  = (float*)(smem + SMEM_SWT);

    if (tid < 128) {
        int j = m0 + tid;
        int jj = (j < cnt) ? j : (cnt - 1);   // clamp padded rows
        srow[tid] = g_idx[e * CAP + jj];
        swt[tid]  = g_wgt[e * CAP + jj];
    }
    __syncthreads();

    const uint32_t sA = smem_u32(smem) + SMEM_A_OFF;
    const uint32_t sB = smem_u32(smem) + SMEM_B_OFF;

    // ---- cp.async assignment: thread owns row tid>>1, chunks {c0, c0+1} ----
    const int lr_ = tid >> 1;
    const int cc0 = (tid & 1) * 2;
    const uint32_t swz = ((uint32_t)(lr_ >> 1) & 3u);
    const uint32_t dstA0 = lr_ * 64 + (((uint32_t)cc0 ^ swz) << 4);
    const uint32_t dstA1 = lr_ * 64 + (((uint32_t)(cc0 + 1) ^ swz) << 4);
    const __half* srcA;
    if (MODE == 1) srcA = g_xh + (size_t)srow[lr_] * HD + cc0 * 8;
    else           srcA = g_hid + (size_t)(hb + lr_) * FH + cc0 * 8;
    const __half* wh = (MODE == 1) ? g_w1h : g_w2h;
    const __half* srcB = wh + ((size_t)e * NB + n0 + lr_) * KTOT + cc0 * 8;

    auto issue = [&](int s, int kt) {
        const uint32_t as = sA + s * STG_BYTES;
        const uint32_t bs = sB + s * STG_BYTES;
        const __half* pa = srcA + kt * 32;
        const __half* pb = srcB + kt * 32;
        CP_ASYNC16(as + dstA0, pa);
        CP_ASYNC16(as + dstA1, pa + 8);
        CP_ASYNC16(bs + dstA0, pb);
        CP_ASYNC16(bs + dstA1, pb + 8);
        CP_COMMIT();
    };

    issue(0, 0); issue(1, 1); issue(2, 2);

    // ---- fragment addressing ----
    const int warp_m = wid & 1, warp_n = wid >> 1;      // 2 x 4 warps, 64x32 each
    const int a_row_off = warp_m * 64 + (lane & 7) + ((lane >> 3) & 1) * 8;
    const int a_chunk_hi = lane >> 4;                    // 0/1
    const int b_row_off = warp_n * 32 + (lane & 7) + ((lane >> 4) << 3);
    const int b_chunk_hi = (lane >> 3) & 1;

    float acc[4][4][4];
#pragma unroll
    for (int i = 0; i < 4; i++)
#pragma unroll
        for (int j = 0; j < 4; j++)
#pragma unroll
            for (int q = 0; q < 4; q++) acc[i][j][q] = 0.f;

    for (int kt = 0; kt < KT; kt++) {
        if (kt < KT - 2)      asm volatile("cp.async.wait_group 2;" ::: "memory");
        else if (kt == KT - 2) asm volatile("cp.async.wait_group 1;" ::: "memory");
        else                   asm volatile("cp.async.wait_group 0;" ::: "memory");
        __syncthreads();
        if (kt + 3 < KT) issue((kt + 3) & 3, kt + 3);

        const uint32_t as = sA + (kt & 3) * STG_BYTES;
        const uint32_t bs = sB + (kt & 3) * STG_BYTES;
#pragma unroll
        for (int ks = 0; ks < 2; ks++) {
            uint32_t af[4][4];
#pragma unroll
            for (int ms = 0; ms < 4; ms++) {
                const int row = a_row_off + ms * 16;
                const uint32_t ch = (uint32_t)(2 * ks + a_chunk_hi);
                const uint32_t ad = as + row * 64 + ((ch ^ ((uint32_t)(row >> 1) & 3u)) << 4);
                LDSM4(af[ms][0], af[ms][1], af[ms][2], af[ms][3], ad);
            }
            uint32_t bf[4][2];
#pragma unroll
            for (int np = 0; np < 2; np++) {
                const int row = b_row_off + np * 16;
                const uint32_t ch = (uint32_t)(2 * ks + b_chunk_hi);
                const uint32_t bd = bs + row * 64 + ((ch ^ ((uint32_t)(row >> 1) & 3u)) << 4);
                uint32_t r0, r1, r2, r3;
                LDSM4(r0, r1, r2, r3, bd);
                bf[np * 2 + 0][0] = r0; bf[np * 2 + 0][1] = r1;
                bf[np * 2 + 1][0] = r2; bf[np * 2 + 1][1] = r3;
            }
#pragma unroll
            for (int ms = 0; ms < 4; ms++)
#pragma unroll
                for (int ns = 0; ns < 4; ns++)
                    mma16816(acc[ms][ns], af[ms], bf[ns]);
        }
        __syncthreads();
    }

    // ---- epilogue ----
    const int g = lane >> 2, tg = lane & 3;
#pragma unroll
    for (int ms = 0; ms < 4; ms++) {
        const int r0_ = warp_m * 64 + ms * 16 + g;
        const int r1_ = r0_ + 8;
#pragma unroll
        for (int ns = 0; ns < 4; ns++) {
            const int col = n0 + warp_n * 32 + ns * 8 + tg * 2;
            if (MODE == 1) {
                const float wA = swt[r0_], wB = swt[r1_];
                float v0 = fmaxf(acc[ms][ns][0], 0.f);
                float v1 = fmaxf(acc[ms][ns][1], 0.f);
                float v2 = fmaxf(acc[ms][ns][2], 0.f);
                float v3 = fmaxf(acc[ms][ns][3], 0.f);
                __half2 h0 = __floats2half2_rn(v0 * v0 * wA, v1 * v1 * wA);
                __half2 h1 = __floats2half2_rn(v2 * v2 * wB, v3 * v3 * wB);
                *(__half2*)&g_hid[(size_t)(hb + r0_) * FH + col] = h0;
                *(__half2*)&g_hid[(size_t)(hb + r1_) * FH + col] = h1;
            } else {
                *(float2*)&g_o2[(size_t)(hb + r0_) * HD + col] =
                    make_float2(acc[ms][ns][0], acc[ms][ns][1]);
                *(float2*)&g_o2[(size_t)(hb + r1_) * HD + col] =
                    make_float2(acc[ms][ns][2], acc[ms][ns][3]);
            }
        }
    }
}

// ---------------- launch ----------------
extern "C" void kernel_launch(void* const* d_in, const int* in_sizes, int n_in,
                              void* d_out, int out_size) {
    const float* x  = (const float*)d_in[0];   // [4,2048,1024]
    const float* gw = (const float*)d_in[1];   // [1024,8]
    const float* w1 = (const float*)d_in[2];   // [8,1024,4096]
    const float* w2 = (const float*)d_in[3];   // [8,4096,1024]
    float* out = (float*)d_out;                // f32 [4,2048,1024]
    (void)in_sizes; (void)n_in; (void)out_size;

    cudaFuncSetAttribute(moe_hgemm_kernel<1>,
                         cudaFuncAttributeMaxDynamicSharedMemorySize, SMEM_TOTAL);
    cudaFuncSetAttribute(moe_hgemm_kernel<2>,
                         cudaFuncAttributeMaxDynamicSharedMemorySize, SMEM_TOTAL);

    init_counts_kernel<<<1, 32>>>();
    router_kernel<<<T_ / 8, 256>>>(x, gw);
    convert_x_kernel<<<(T_ * HD / 4) / 256, 256>>>((const float4*)x);
    transpose_half_kernel<1><<<dim3(FH / 32, HD / 32, E_), dim3(32, 8)>>>(w1);
    transpose_half_kernel<2><<<dim3(HD / 32, FH / 32, E_), dim3(32, 8)>>>(w2);
    calc_offsets_kernel<<<1, 1>>>();

    moe_hgemm_kernel<1><<<dim3(FH / 128, CAP / 128, E_), 256, SMEM_TOTAL>>>();
    moe_hgemm_kernel<2><<<dim3(HD / 128, CAP / 128, E_), 256, SMEM_TOTAL>>>();
    combine_kernel<<<T_, 256>>>(out);
}